// round 6
// baseline (speedup 1.0000x reference)
#include <cuda_runtime.h>

// EEG_SimpleLSM: 3-layer LIF winner-take-all liquid state machine.
// x: [256, 32, 4000] f32, W1: [64,32], W2: [128,64]. Output: exp(pre_v2@T-1) [256,128].
//
// Body = round-3 champion, UNTOUCHED (software-pipelined L2(t)/L1(t+1)/L0(t+2),
// Markstein constant division, REDUX max + REDUX min first-index tie-break).
//
// ROUND 6: launch geometry only. Round 3 ran 256 single-warp CTAs: their only
// warp lands on SMSP 0, and 108 of 148 SMs host 2 CTAs -> two ~0.85-IPC warps
// fight for one scheduler (1.7x demand) and set the kernel time. Now: 64-thread
// CTAs, warp w = sample 2*blockIdx+w, grid 128 -> exactly 1 CTA per SM, warps
// on SMSP 0 and 1, zero scheduler contention. (Round 2 tested this layout but
// simultaneously rewrote the argmax to ballot/ffs, which wrecked codegen; this
// isolates the layout variable on known-good code.)

#define NB   256
#define NCH  32
#define NT   4000

__device__ __align__(16) float g_W1T[32 * 64];   // W1T[c][j] = W1[j][c]
__device__ __align__(16) float g_W2T[64 * 128];  // W2T[c][j] = W2[j][c]

__global__ void prep_kernel(const float* __restrict__ W1, const float* __restrict__ W2) {
    int tid = blockIdx.x * blockDim.x + threadIdx.x;
    int nthr = blockDim.x * gridDim.x;
    for (int i = tid; i < 64 * 32; i += nthr) {
        int r = i >> 5, c = i & 31;
        g_W1T[c * 64 + r] = W1[i];
    }
    for (int i = tid; i < 128 * 64; i += nthr) {
        int r = i >> 6, c = i & 63;
        g_W2T[c * 128 + r] = W2[i];
    }
}

// Correctly-rounded division by constant c (rc = RN(1/c)), Markstein sequence.
__device__ __forceinline__ float divc(float v, float c, float rc) {
    float q = v * rc;
    float r = __fmaf_rn(-c, q, v);
    return __fmaf_rn(r, rc, q);
}

// Monotone key: strictly order-preserving float -> unsigned mapping.
__device__ __forceinline__ unsigned fkey(float v) {
    unsigned b = __float_as_uint(v);
    return b ^ ((unsigned)((int)b >> 31) | 0x80000000u);
}

// key(1.5f): 0x3FC00000 -> 0xBFC00000 ; key(1.2f): 0x3F99999A -> 0xBF99999A
#define KEY_VTH0 0xBFC00000u
#define KEY_VTH1 0xBF99999Au

// ---- pipeline stages (identical to round 3) ----

__device__ __forceinline__ void stage0(float xv, int lane, float& v0,
                                       float& s0_out, unsigned& idx0_out) {
    float d0  = divc(v0, 3.0f, 1.0f / 3.0f);
    float ch0 = (v0 + xv) - d0;
    unsigned k0   = fkey(ch0);
    unsigned m0   = __reduce_max_sync(0xFFFFFFFFu, k0);
    unsigned cand = (k0 == m0) ? (unsigned)lane : 32u;
    idx0_out = __reduce_min_sync(0xFFFFFFFFu, cand);
    s0_out   = (m0 >= KEY_VTH0) ? 1.0f : 0.0f;
    v0 = (ch0 >= 1.5f) ? 0.0f : ch0;
}

__device__ __forceinline__ void stage1(const float2* __restrict__ w1p, int lane,
                                       unsigned idx0, float s0,
                                       float& v1a, float& v1b,
                                       float& s1_out, unsigned& idx1_out) {
    const float RCT = 1.0f / 80000.0f;
    float2 w1 = __ldg(w1p + (idx0 << 5) + lane);   // W1T[idx0][2l..2l+1]
    float d1a = divc(v1a, 80000.0f, RCT);
    float d1b = divc(v1b, 80000.0f, RCT);
    float cha = __fmaf_rn(w1.x, s0, v1a) - d1a;    // exact: s0 in {0,1}
    float chb = __fmaf_rn(w1.y, s0, v1b) - d1b;
    unsigned ka = fkey(cha);
    unsigned kb = fkey(chb);
    bool bw = kb > ka;
    unsigned lk = bw ? kb : ka;
    unsigned li = 2u * (unsigned)lane + (bw ? 1u : 0u);
    unsigned m1   = __reduce_max_sync(0xFFFFFFFFu, lk);
    unsigned cand = (lk == m1) ? li : 64u;
    idx1_out = __reduce_min_sync(0xFFFFFFFFu, cand);
    s1_out   = (m1 >= KEY_VTH1) ? 1.0f : 0.0f;
    v1a = (cha >= 1.2f) ? 0.0f : cha;
    v1b = (chb >= 1.2f) ? 0.0f : chb;
}

__device__ __forceinline__ void stage2(const float4* __restrict__ w2p, int lane,
                                       unsigned idx1, float s1,
                                       float4& v2, float4& pc) {
    const float RCT = 1.0f / 80000.0f;
    float4 w2 = __ldg(w2p + (idx1 << 5) + lane);   // W2T[idx1][4l..4l+3]
    float dx = divc(v2.x, 80000.0f, RCT);
    float dy = divc(v2.y, 80000.0f, RCT);
    float dz = divc(v2.z, 80000.0f, RCT);
    float dw = divc(v2.w, 80000.0f, RCT);
    pc.x = __fmaf_rn(w2.x, s1, v2.x) - dx;
    pc.y = __fmaf_rn(w2.y, s1, v2.y) - dy;
    pc.z = __fmaf_rn(w2.z, s1, v2.z) - dz;
    pc.w = __fmaf_rn(w2.w, s1, v2.w) - dw;
    v2.x = (pc.x >= 1.2f) ? 0.0f : pc.x;
    v2.y = (pc.y >= 1.2f) ? 0.0f : pc.y;
    v2.z = (pc.z >= 1.2f) ? 0.0f : pc.z;
    v2.w = (pc.w >= 1.2f) ? 0.0f : pc.w;
}

__global__ void __launch_bounds__(64)
lsm_kernel(const float* __restrict__ x, float* __restrict__ out) {
    const int lane = threadIdx.x & 31;
    const int b    = (blockIdx.x << 1) + (threadIdx.x >> 5);

    // Per-lane state
    float v0  = 0.0f;
    float v1a = 0.0f, v1b = 0.0f;
    float4 v2 = make_float4(0.f, 0.f, 0.f, 0.f);
    float4 pc = make_float4(0.f, 0.f, 0.f, 0.f);

    // Pipeline tokens. Zero tokens make the first one/two L1/L2 executions
    // exact no-ops on all-zero state (they emit zero tokens themselves).
    float    s0_d = 0.0f;  unsigned idx0_d = 0u;
    float    s1_d = 0.0f;  unsigned idx1_d = 0u;

    const float4* xp  = reinterpret_cast<const float4*>(x + (size_t)b * (NCH * NT) + lane * NT);
    const float2* w1p = reinterpret_cast<const float2*>(g_W1T);
    const float4* w2p = reinterpret_cast<const float4*>(g_W2T);

    float4 c0 = __ldg(xp + 0);
    float4 c1 = __ldg(xp + 1);

    const int NBLK = NT / 8;  // 500
    for (int blk = 0; blk < NBLK; ++blk) {
        int nb = (blk + 1 < NBLK) ? (blk + 1) * 2 : 0;
        float4 n0 = __ldg(xp + nb);
        float4 n1 = __ldg(xp + nb + 1);

        float xs[8] = {c0.x, c0.y, c0.z, c0.w, c1.x, c1.y, c1.z, c1.w};

#pragma unroll
        for (int j = 0; j < 8; ++j) {
            // L2 lags 2 steps, L1 lags 1 step, L0 is current. All three are
            // mutually independent within this iteration -> full overlap.
            stage2(w2p, lane, idx1_d, s1_d, v2, pc);
            stage1(w1p, lane, idx0_d, s0_d, v1a, v1b, s1_d, idx1_d);
            stage0(xs[j], lane, v0, s0_d, idx0_d);
        }

        c0 = n0;
        c1 = n1;
    }

    // Drain the pipeline: L2(T-2), L1(T-1), L2(T-1).
    stage2(w2p, lane, idx1_d, s1_d, v2, pc);
    stage1(w1p, lane, idx0_d, s0_d, v1a, v1b, s1_d, idx1_d);
    stage2(w2p, lane, idx1_d, s1_d, v2, pc);

    // liquid state: exp of last-step pre-reset v2
    float4 o;
    o.x = expf(pc.x);
    o.y = expf(pc.y);
    o.z = expf(pc.z);
    o.w = expf(pc.w);
    reinterpret_cast<float4*>(out + (size_t)b * 128)[lane] = o;
}

extern "C" void kernel_launch(void* const* d_in, const int* in_sizes, int n_in,
                              void* d_out, int out_size) {
    const float* x  = (const float*)d_in[0];
    const float* W1 = (const float*)d_in[1];
    const float* W2 = (const float*)d_in[2];
    float* out = (float*)d_out;

    prep_kernel<<<1, 256>>>(W1, W2);
    lsm_kernel<<<NB / 2, 64>>>(x, out);
}

// round 7
// speedup vs baseline: 2.2618x; 2.2618x over previous
#include <cuda_runtime.h>

// EEG_SimpleLSM: 3-layer LIF winner-take-all liquid state machine.
// x: [256, 32, 4000] f32, W1: [64,32], W2: [128,64]. Output: exp(pre_v2@T-1) [256,128].
//
// ROUND 7: producer/consumer warp split with DEEP chunks. L2 consumes (s1,idx1)
// tokens and feeds nothing back -> one-way stream. Per sample:
//   Warp A: R3-champion L0+L1 pipeline (stage1 consumes previous step's s0),
//           emits one packed token per step into smem.
//   Warp B: replays L2 one chunk (80 steps) behind; all 80 token loads are
//           independent -> no serialization behind the barrier (R4's mistake
//           was 8-step batches with a BAR each).
// 50 chunk syncs total. 128 thr = 2 samples x (A,B); warps 0..3 -> SMSPs 0..3
// (no scheduler sharing); grid 128 -> 1 CTA/SM. __launch_bounds__(128, 1)
// prevents the 40-reg ptxas occupancy heuristic that sank R2/R4/R6 (every
// >=64-thr build got 40 regs / IPC 0.6; 32-thr builds got 64 regs / IPC 0.85).
//
// Token for step t-1 is produced by A's stage1 at iteration t (R3 skew).
// B's chunk c covers L2 steps c*80-1 .. c*80+78; slot j <-> step c*80-1+j.
// Step -1 is the all-zero token (exact no-op on zero state, as in R3).
// Last step 3999's token is emitted in A's epilogue iteration.
// Every stage execution is bit-identical to round 3 -> rel_err must stay
// exactly 4.882994e-08.

#define NB    256
#define NCH   32
#define NT    4000
#define CHUNK 80
#define NCHK  (NT / CHUNK)     // 50
#define NBLK8 (NT / 8)         // 500

__device__ __align__(16) float g_W1T[32 * 64];   // W1T[c][j] = W1[j][c]
__device__ __align__(16) float g_W2T[64 * 128];  // W2T[c][j] = W2[j][c]

__global__ void prep_kernel(const float* __restrict__ W1, const float* __restrict__ W2) {
    int tid = blockIdx.x * blockDim.x + threadIdx.x;
    int nthr = blockDim.x * gridDim.x;
    for (int i = tid; i < 64 * 32; i += nthr) {
        int r = i >> 5, c = i & 31;
        g_W1T[c * 64 + r] = W1[i];
    }
    for (int i = tid; i < 128 * 64; i += nthr) {
        int r = i >> 6, c = i & 63;
        g_W2T[c * 128 + r] = W2[i];
    }
}

// Correctly-rounded division by constant c (rc = RN(1/c)), Markstein sequence.
__device__ __forceinline__ float divc(float v, float c, float rc) {
    float q = v * rc;
    float r = __fmaf_rn(-c, q, v);
    return __fmaf_rn(r, rc, q);
}

// Monotone key: strictly order-preserving float -> unsigned mapping.
__device__ __forceinline__ unsigned fkey(float v) {
    unsigned b = __float_as_uint(v);
    return b ^ ((unsigned)((int)b >> 31) | 0x80000000u);
}

// key(1.5f): 0x3FC00000 -> 0xBFC00000 ; key(1.2f): 0x3F99999A -> 0xBF99999A
#define KEY_VTH0 0xBFC00000u
#define KEY_VTH1 0xBF99999Au

// ---- stages (identical arithmetic to round 3) ----

__device__ __forceinline__ void stage0(float xv, int lane, float& v0,
                                       float& s0_out, unsigned& idx0_out) {
    float d0  = divc(v0, 3.0f, 1.0f / 3.0f);
    float ch0 = (v0 + xv) - d0;
    unsigned k0   = fkey(ch0);
    unsigned m0   = __reduce_max_sync(0xFFFFFFFFu, k0);
    unsigned cand = (k0 == m0) ? (unsigned)lane : 32u;
    idx0_out = __reduce_min_sync(0xFFFFFFFFu, cand);
    s0_out   = (m0 >= KEY_VTH0) ? 1.0f : 0.0f;
    v0 = (ch0 >= 1.5f) ? 0.0f : ch0;
}

// stage1 returning packed token (idx1 | s1<<31)
__device__ __forceinline__ unsigned stage1_tok(const float2* __restrict__ w1p, int lane,
                                               unsigned idx0, float s0,
                                               float& v1a, float& v1b) {
    const float RCT = 1.0f / 80000.0f;
    float2 w1 = __ldg(w1p + (idx0 << 5) + lane);   // W1T[idx0][2l..2l+1]
    float d1a = divc(v1a, 80000.0f, RCT);
    float d1b = divc(v1b, 80000.0f, RCT);
    float cha = __fmaf_rn(w1.x, s0, v1a) - d1a;    // exact: s0 in {0,1}
    float chb = __fmaf_rn(w1.y, s0, v1b) - d1b;
    unsigned ka = fkey(cha);
    unsigned kb = fkey(chb);
    bool bw = kb > ka;
    unsigned lk = bw ? kb : ka;
    unsigned li = 2u * (unsigned)lane + (bw ? 1u : 0u);
    unsigned m1   = __reduce_max_sync(0xFFFFFFFFu, lk);
    unsigned cand = (lk == m1) ? li : 64u;
    unsigned idx1 = __reduce_min_sync(0xFFFFFFFFu, cand);
    unsigned tok  = idx1 | ((m1 >= KEY_VTH1) ? 0x80000000u : 0u);
    v1a = (cha >= 1.2f) ? 0.0f : cha;
    v1b = (chb >= 1.2f) ? 0.0f : chb;
    return tok;
}

__device__ __forceinline__ void stage2_tok(const float4* __restrict__ w2p, int lane,
                                           unsigned tok, float4& v2, float4& pc) {
    const float RCT = 1.0f / 80000.0f;
    unsigned idx1 = tok & 0x7FFFFFFFu;
    float s1 = (tok & 0x80000000u) ? 1.0f : 0.0f;
    float4 w2 = __ldg(w2p + (idx1 << 5) + lane);   // W2T[idx1][4l..4l+3]
    float dx = divc(v2.x, 80000.0f, RCT);
    float dy = divc(v2.y, 80000.0f, RCT);
    float dz = divc(v2.z, 80000.0f, RCT);
    float dw = divc(v2.w, 80000.0f, RCT);
    pc.x = __fmaf_rn(w2.x, s1, v2.x) - dx;
    pc.y = __fmaf_rn(w2.y, s1, v2.y) - dy;
    pc.z = __fmaf_rn(w2.z, s1, v2.z) - dz;
    pc.w = __fmaf_rn(w2.w, s1, v2.w) - dw;
    v2.x = (pc.x >= 1.2f) ? 0.0f : pc.x;
    v2.y = (pc.y >= 1.2f) ? 0.0f : pc.y;
    v2.z = (pc.z >= 1.2f) ? 0.0f : pc.z;
    v2.w = (pc.w >= 1.2f) ? 0.0f : pc.w;
}

__global__ void __launch_bounds__(128, 1)
lsm_kernel(const float* __restrict__ x, float* __restrict__ out) {
    // tokens: [sample][buffer][step-in-chunk]
    __shared__ unsigned s_tok[2][2][CHUNK];

    const int tid  = threadIdx.x;
    const int lane = tid & 31;
    const int warp = tid >> 5;
    const int samp = warp >> 1;
    const int role = warp & 1;          // 0 = A (L0+L1 producer), 1 = B (L2 consumer)
    const int b    = (blockIdx.x << 1) + samp;

    // A state
    float v0 = 0.0f, v1a = 0.0f, v1b = 0.0f;
    float s0_d = 0.0f; unsigned idx0_d = 0u;
    float4 c0, c1;
    int gblk = 0;
    // B state
    float4 v2 = make_float4(0.f, 0.f, 0.f, 0.f);
    float4 pc = make_float4(0.f, 0.f, 0.f, 0.f);

    const float4* xp  = reinterpret_cast<const float4*>(x + (size_t)b * (NCH * NT) + lane * NT);
    const float2* w1p = reinterpret_cast<const float2*>(g_W1T);
    const float4* w2p = reinterpret_cast<const float4*>(g_W2T);

    if (role == 0) { c0 = __ldg(xp); c1 = __ldg(xp + 1); }

    for (int c = 0; c <= NCHK; ++c) {
        if (role == 0) {
            if (c < NCHK) {
                // ---- A: produce chunk c (80 steps, 10 blocks of 8) ----
                unsigned* tb = &s_tok[samp][c & 1][0];
                for (int k = 0; k < CHUNK / 8; ++k) {
                    int nb = (gblk + 1 < NBLK8) ? (gblk + 1) * 2 : 0;
                    float4 n0 = __ldg(xp + nb);
                    float4 n1 = __ldg(xp + nb + 1);
                    float xs[8] = {c0.x, c0.y, c0.z, c0.w, c1.x, c1.y, c1.z, c1.w};
#pragma unroll
                    for (int j = 0; j < 8; ++j) {
                        // stage1 consumes previous step's (s0,idx0) -> token
                        // for step (global-1); then stage0 produces fresh s0.
                        unsigned tok = stage1_tok(w1p, lane, idx0_d, s0_d, v1a, v1b);
                        if (lane == 0) tb[k * 8 + j] = tok;
                        stage0(xs[j], lane, v0, s0_d, idx0_d);
                    }
                    c0 = n0; c1 = n1; ++gblk;
                }
            } else {
                // ---- A epilogue: token for the final step (NT-1) ----
                unsigned tok = stage1_tok(w1p, lane, idx0_d, s0_d, v1a, v1b);
                if (lane == 0) s_tok[samp][0][0] = tok;
            }
        } else {
            if (c >= 1) {
                // ---- B: consume chunk c-1 (L2 steps (c-1)*80-1 .. (c-1)*80+78) ----
                const unsigned* tb = &s_tok[samp][(c - 1) & 1][0];
#pragma unroll 4
                for (int j = 0; j < CHUNK; ++j)
                    stage2_tok(w2p, lane, tb[j], v2, pc);
            }
        }
        __syncthreads();
    }

    if (role == 1) {
        // B: final L2 step (NT-1) from A's epilogue token, then output.
        stage2_tok(w2p, lane, s_tok[samp][0][0], v2, pc);
        float4 o;
        o.x = expf(pc.x);
        o.y = expf(pc.y);
        o.z = expf(pc.z);
        o.w = expf(pc.w);
        reinterpret_cast<float4*>(out + (size_t)b * 128)[lane] = o;
    }
}

extern "C" void kernel_launch(void* const* d_in, const int* in_sizes, int n_in,
                              void* d_out, int out_size) {
    const float* x  = (const float*)d_in[0];
    const float* W1 = (const float*)d_in[1];
    const float* W2 = (const float*)d_in[2];
    float* out = (float*)d_out;

    prep_kernel<<<1, 256>>>(W1, W2);
    lsm_kernel<<<NB / 2, 128>>>(x, out);
}